// round 15
// baseline (speedup 1.0000x reference)
#include <cuda_runtime.h>
#include <cuda_bf16.h>
#include <cuda_fp16.h>
#include <stdint.h>
#include <cstdint>
#include <math.h>

// MMD loss: persistent FP8(e4m3) mma.sync, f16 accumulators, half2 screen,
// exact-fp32 slow path, fused last-block finalize.
// This round: loop-invariant ldsm addressing (base + (h32 ^ (ks<<5))).
// z: [8192, 256] fp32. gamma = 0.5.

#define NROWS 8192
#define DIM   256
#define BM    128
#define BN    128
#define NTHREADS 256
#define NBLK   304            // 2 persistent CTAs per SM
#define TPB    6              // 2080 = 304*6 + 256
#define TREM   256

// SMEM (bytes). fp8 tile: 128 rows x 256 B = 32 KB.
#define SM_A    0
#define SM_B0   32768
#define SM_B1   65536
#define SM_SQI  98304
#define SM_SQJ  (98304 + 512)
#define SM_RED  (98304 + 1024)
#define SMEM_TOTAL (98304 + 2048)

__device__ uint8_t  g_z8[NROWS * DIM];    // e4m3
__device__ float    g_sq[NROWS];
__device__ double   g_accum;              // term_a numerator  (reset by last block)
__device__ float    g_termb;              // sum exp(-sq/4)    (reset by last block)
__device__ unsigned g_done;               // ticket counter    (reset by last block)

// ---------------------------------------------------------------------------
__device__ __forceinline__ uint32_t smem_u32(const void* p) {
    uint32_t a;
    asm("{ .reg .u64 t; cvta.to.shared.u64 t, %1; cvt.u32.u64 %0, t; }"
        : "=r"(a) : "l"(p));
    return a;
}

__device__ __forceinline__ void cp16(uint32_t s, const void* g) {
    asm volatile("cp.async.cg.shared.global [%0], [%1], 16;"
                 :: "r"(s), "l"(g) : "memory");
}

__device__ __forceinline__ void ldsm4(uint32_t* r, uint32_t addr) {
    asm volatile("ldmatrix.sync.aligned.m8n8.x4.shared.b16 {%0,%1,%2,%3}, [%4];"
                 : "=r"(r[0]), "=r"(r[1]), "=r"(r[2]), "=r"(r[3])
                 : "r"(addr));
}

__device__ __forceinline__ void mma_fp8_h(uint32_t* d, const uint32_t* a,
                                          const uint32_t* b) {
    asm volatile(
        "mma.sync.aligned.m16n8k32.row.col.f16.e4m3.e4m3.f16 "
        "{%0,%1}, {%2,%3,%4,%5}, {%6,%7}, {%0,%1};"
        : "+r"(d[0]), "+r"(d[1])
        : "r"(a[0]), "r"(a[1]), "r"(a[2]), "r"(a[3]),
          "r"(b[0]), "r"(b[1]));
}

__device__ __forceinline__ uint32_t sw_off(int row, int kc16) {
    return (uint32_t)row * 256u + (uint32_t)((kc16 ^ (row & 7)) << 4);
}

__device__ __forceinline__ void load_tile(uint32_t dst, const uint8_t* src,
                                          int tid) {
    #pragma unroll
    for (int t = 0; t < 8; t++) {
        int idx = tid + t * NTHREADS;
        int row = idx >> 4;
        int kc  = idx & 15;
        cp16(dst + sw_off(row, kc), src + row * DIM + kc * 16);
    }
}

// exact fp32 recompute for screened-in pairs (cold path)
__device__ __noinline__ float exact_pair(const float* __restrict__ zf,
                                         int ig, int jg, float sqsum) {
    const float* zi = zf + (size_t)ig * DIM;
    const float* zj = zf + (size_t)jg * DIM;
    float dot = 0.0f;
    for (int k = 0; k < DIM; k++)
        dot = fmaf(zi[k], zj[k], dot);
    float de = fmaxf(sqsum - 2.0f * dot, 0.0f);
    return 2.0f * expf(-0.5f * de);
}

// ---------------------------------------------------------------------------
// Kernel 1: fp32 -> e4m3, exact fp32 row norms, term_b partial sums.
// ---------------------------------------------------------------------------
__global__ void __launch_bounds__(256) prep_kernel(const float* __restrict__ z)
{
    __shared__ float tb_red[8];

    const int w2   = (blockIdx.x * blockDim.x + threadIdx.x) >> 5;
    const int wloc = threadIdx.x >> 5;
    const int lane = threadIdx.x & 31;
    const int r0 = w2 * 2, r1 = r0 + 1;

    float tb = 0.0f;
    if (r0 < NROWS) {
        const float4* rowA = (const float4*)(z + (size_t)r0 * DIM);
        const float4* rowB = (const float4*)(z + (size_t)r1 * DIM);
        float4 a0 = rowA[lane * 2], b0 = rowA[lane * 2 + 1];
        float4 a1 = rowB[lane * 2], b1 = rowB[lane * 2 + 1];

        float s0 = a0.x*a0.x + a0.y*a0.y + a0.z*a0.z + a0.w*a0.w
                 + b0.x*b0.x + b0.y*b0.y + b0.z*b0.z + b0.w*b0.w;
        float s1 = a1.x*a1.x + a1.y*a1.y + a1.z*a1.z + a1.w*a1.w
                 + b1.x*b1.x + b1.y*b1.y + b1.z*b1.z + b1.w*b1.w;

        uint16_t p0, p1, p2, p3;
        asm("cvt.rn.satfinite.e4m3x2.f32 %0, %1, %2;" : "=h"(p0) : "f"(a0.y), "f"(a0.x));
        asm("cvt.rn.satfinite.e4m3x2.f32 %0, %1, %2;" : "=h"(p1) : "f"(a0.w), "f"(a0.z));
        asm("cvt.rn.satfinite.e4m3x2.f32 %0, %1, %2;" : "=h"(p2) : "f"(b0.y), "f"(b0.x));
        asm("cvt.rn.satfinite.e4m3x2.f32 %0, %1, %2;" : "=h"(p3) : "f"(b0.w), "f"(b0.z));
        uint2 pk0;
        pk0.x = (uint32_t)p0 | ((uint32_t)p1 << 16);
        pk0.y = (uint32_t)p2 | ((uint32_t)p3 << 16);
        *(uint2*)(g_z8 + (size_t)r0 * DIM + lane * 8) = pk0;

        asm("cvt.rn.satfinite.e4m3x2.f32 %0, %1, %2;" : "=h"(p0) : "f"(a1.y), "f"(a1.x));
        asm("cvt.rn.satfinite.e4m3x2.f32 %0, %1, %2;" : "=h"(p1) : "f"(a1.w), "f"(a1.z));
        asm("cvt.rn.satfinite.e4m3x2.f32 %0, %1, %2;" : "=h"(p2) : "f"(b1.y), "f"(b1.x));
        asm("cvt.rn.satfinite.e4m3x2.f32 %0, %1, %2;" : "=h"(p3) : "f"(b1.w), "f"(b1.z));
        uint2 pk1;
        pk1.x = (uint32_t)p0 | ((uint32_t)p1 << 16);
        pk1.y = (uint32_t)p2 | ((uint32_t)p3 << 16);
        *(uint2*)(g_z8 + (size_t)r1 * DIM + lane * 8) = pk1;

        #pragma unroll
        for (int o = 16; o > 0; o >>= 1) {
            s0 += __shfl_xor_sync(0xFFFFFFFFu, s0, o);
            s1 += __shfl_xor_sync(0xFFFFFFFFu, s1, o);
        }
        if (lane == 0) {
            g_sq[r0] = s0; g_sq[r1] = s1;
            tb = __expf(-0.25f * s0) + __expf(-0.25f * s1);
        }
    }

    if (lane == 0) tb_red[wloc] = tb;
    __syncthreads();
    if (threadIdx.x == 0) {
        float s = 0.0f;
        #pragma unroll
        for (int i = 0; i < 8; i++) s += tb_red[i];
        atomicAdd(&g_termb, s);
    }
}

// ---------------------------------------------------------------------------
// Kernel 2: persistent symmetric Gram + fused last-block finalize.
// ---------------------------------------------------------------------------
__global__ void __launch_bounds__(NTHREADS, 2)
gram_kernel(const float* __restrict__ zf, float* __restrict__ out)
{
    const int p = blockIdx.x;
    const int t0  = p * TPB + (p < TREM ? p : TREM);
    const int cnt = TPB + (p < TREM ? 1 : 0);
    const int t1  = t0 + cnt;

    extern __shared__ char smem[];
    const uint32_t sb  = smem_u32(smem);
    const int tid  = threadIdx.x;
    const int wid  = tid >> 5;
    const int lane = tid & 31;

    int bi = 0, s = 0;
    while (s + (64 - bi) <= t0) { s += 64 - bi; bi++; }
    int bj = bi + (t0 - s);

    float* sqi_s = (float*)(smem + SM_SQI);
    float* sqj_s = (float*)(smem + SM_SQJ);

    load_tile(sb + SM_B0, g_z8 + (size_t)bj * BN * DIM, tid);
    asm volatile("cp.async.commit_group;" ::: "memory");

    const int wm = (wid & 3) * 32;
    const int wn = (wid >> 2) * 64;
    const int t4 = lane >> 2;
    const int t2 = (lane & 3) << 1;

    // ---- loop-invariant ldsm base addresses --------------------------------
    // sw byte offset for kc=2*ks+delta decomposes as:
    //   row*256 + ((delta ^ (lane&1))<<4)  +  ((ks<<5) ^ h32),
    // h32 = ((lane&7)>>1)<<5   (same for all six fragments of this lane).
    const uint32_t h32 = (uint32_t)(((lane & 7) >> 1) << 5);
    const uint32_t lo  = (uint32_t)(lane & 1);

    uint32_t a_base[2];
    #pragma unroll
    for (int mi = 0; mi < 2; mi++) {
        int row = wm + mi * 16 + (lane & 15);
        a_base[mi] = sb + SM_A + (uint32_t)row * 256u
                   + ((((uint32_t)(lane >> 4)) ^ lo) << 4);
    }
    uint32_t b_base[2][4];
    #pragma unroll
    for (int bsel = 0; bsel < 2; bsel++)
        #pragma unroll
        for (int nq = 0; nq < 4; nq++) {
            int row = wn + nq * 16 + (lane & 7) + ((lane >> 4) << 3);
            b_base[bsel][nq] = sb + (bsel ? SM_B1 : SM_B0)
                             + (uint32_t)row * 256u
                             + ((((uint32_t)(lane >> 3) & 1u) ^ lo) << 4);
        }

    int   loaded_bi = -1;
    int   buf = 0;
    float local = 0.0f;

    for (int t = t0; t < t1; t++) {
        asm volatile("cp.async.wait_group 0;" ::: "memory");
        __syncthreads();

        const bool a_new = (bi != loaded_bi);
        if (a_new) {
            load_tile(sb + SM_A, g_z8 + (size_t)bi * BM * DIM, tid);
            asm volatile("cp.async.commit_group;" ::: "memory");
            loaded_bi = bi;
            if (tid < 128) sqi_s[tid] = g_sq[bi * BM + tid];
        }
        if (tid < 128) sqj_s[tid] = g_sq[bj * BN + tid];

        int nbi = bi, nbj = bj + 1;
        if (nbj == 64) { nbi = bi + 1; nbj = nbi; }
        if (t + 1 < t1) {
            load_tile(sb + (buf ? SM_B0 : SM_B1),
                      g_z8 + (size_t)nbj * BN * DIM, tid);
            asm volatile("cp.async.commit_group;" ::: "memory");
        }
        if (a_new)
            asm volatile("cp.async.wait_group 1;" ::: "memory");
        __syncthreads();

        const bool diag = (bi == bj);
        if (!(diag && wn + 64 <= wm)) {
            const uint32_t* bb = b_base[buf];

            uint32_t acc[2][8][2];
            #pragma unroll
            for (int mi = 0; mi < 2; mi++)
                #pragma unroll
                for (int ni = 0; ni < 8; ni++)
                    acc[mi][ni][0] = acc[mi][ni][1] = 0u;

            uint32_t afr[2][2][4], bfr[2][4][4];
            {   // k-step 0: koff = (0<<5) ^ h32 = h32
                #pragma unroll
                for (int mi = 0; mi < 2; mi++) ldsm4(afr[0][mi], a_base[mi] + h32);
                #pragma unroll
                for (int nq = 0; nq < 4; nq++) ldsm4(bfr[0][nq], bb[nq] + h32);
            }

            #pragma unroll
            for (int ks = 0; ks < 8; ks++) {
                const int cur = ks & 1, nxt = cur ^ 1;
                if (ks < 7) {
                    const uint32_t koff = h32 ^ (uint32_t)((ks + 1) << 5);
                    #pragma unroll
                    for (int mi = 0; mi < 2; mi++)
                        ldsm4(afr[nxt][mi], a_base[mi] + koff);
                    #pragma unroll
                    for (int nq = 0; nq < 4; nq++)
                        ldsm4(bfr[nxt][nq], bb[nq] + koff);
                }
                #pragma unroll
                for (int mi = 0; mi < 2; mi++)
                    #pragma unroll
                    for (int nq = 0; nq < 4; nq++) {
                        mma_fp8_h(acc[mi][nq*2],   afr[cur][mi], &bfr[cur][nq][0]);
                        mma_fp8_h(acc[mi][nq*2+1], afr[cur][mi], &bfr[cur][nq][2]);
                    }
            }

            // ---- vector screen: d2 = ss2 - 2*acc2 in half2; hmin tree ----
            __half2 sqj2[8];
            #pragma unroll
            for (int ni = 0; ni < 8; ni++) {
                int jl0 = wn + ni * 8 + t2;
                sqj2[ni] = __floats2half2_rn(sqj_s[jl0], sqj_s[jl0 + 1]);
            }
            __half2 sqi2[4];
            #pragma unroll
            for (int mi = 0; mi < 2; mi++)
                #pragma unroll
                for (int r = 0; r < 2; r++) {
                    float v = sqi_s[wm + mi * 16 + t4 + r * 8];
                    sqi2[mi * 2 + r] = __float2half2_rn(v);
                }

            const __half2 m2 = __float2half2_rn(-2.0f);
            __half2 dmin = __float2half2_rn(60000.0f);
            #pragma unroll
            for (int mi = 0; mi < 2; mi++)
                #pragma unroll
                for (int ni = 0; ni < 8; ni++)
                    #pragma unroll
                    for (int r = 0; r < 2; r++) {
                        __half2 a2 = *(const __half2*)&acc[mi][ni][r];
                        __half2 d2 = __hfma2(m2, a2,
                                             __hadd2(sqi2[mi*2+r], sqj2[ni]));
                        dmin = __hmin2(dmin, d2);
                    }
            float dm = fminf(__low2float(dmin), __high2float(dmin));

            if (diag || dm < 250.0f) {
                #pragma unroll
                for (int mi = 0; mi < 2; mi++)
                    #pragma unroll
                    for (int ni = 0; ni < 8; ni++)
                        #pragma unroll
                        for (int r = 0; r < 2; r++) {
                            float2 f = __half22float2(
                                *(const __half2*)&acc[mi][ni][r]);
                            int il = wm + mi * 16 + t4 + r * 8;
                            #pragma unroll
                            for (int c = 0; c < 2; c++) {
                                int jl = wn + ni * 8 + t2 + c;
                                float dot = (c == 0) ? f.x : f.y;
                                float ss  = sqi_s[il] + sqj_s[jl];
                                float d   = fmaf(-2.0f, dot, ss);
                                if (d < 250.0f) {
                                    int ig = bi * BM + il, jg = bj * BN + jl;
                                    if (ig == jg) local += 1.0f;
                                    else if (!diag || jl > il)
                                        local += exact_pair(zf, ig, jg, ss);
                                }
                            }
                        }
            }
        }

        bi = nbi; bj = nbj; buf ^= 1;
    }

    // block reduce + one double atomic; last block finalizes and resets
    float* red = (float*)(smem + SM_RED);
    red[tid] = local;
    __syncthreads();
    #pragma unroll
    for (int s2 = NTHREADS / 2; s2 > 0; s2 >>= 1) {
        if (tid < s2) red[tid] += red[tid + s2];
        __syncthreads();
    }
    if (tid == 0) {
        atomicAdd(&g_accum, (double)red[0]);
        __threadfence();
        unsigned ticket = atomicAdd(&g_done, 1u);
        if (ticket == NBLK - 1) {
            __threadfence();
            const double n = (double)NROWS;
            double term_a  = g_accum / (n * n);
            double term_b  = ldexp((double)g_termb / n, -128);
            double term_c  = 1.0 / pow(3.0, 128.0);
            out[0] = (float)(term_a - 2.0 * term_b + term_c);
            g_accum = 0.0;
            g_termb = 0.0f;
            g_done  = 0u;
        }
    }
}

// ---------------------------------------------------------------------------
extern "C" void kernel_launch(void* const* d_in, const int* in_sizes, int n_in,
                              void* d_out, int out_size)
{
    const float* z   = (const float*)d_in[0];
    float*       out = (float*)d_out;

    cudaFuncSetAttribute(gram_kernel,
                         cudaFuncAttributeMaxDynamicSharedMemorySize, SMEM_TOTAL);

    prep_kernel<<<NROWS / 16, 256>>>(z);

    gram_kernel<<<NBLK, NTHREADS, SMEM_TOTAL>>>(z, out);
}

// round 16
// speedup vs baseline: 1.0435x; 1.0435x over previous
#include <cuda_runtime.h>
#include <cuda_bf16.h>
#include <cuda_fp16.h>
#include <stdint.h>
#include <cstdint>
#include <math.h>

// MMD loss: persistent FP8(e4m3) mma.sync, f16 accumulators, cheap
// conservative screen + exact-fp32 slow path, fused last-block finalize.
// z: [8192, 256] fp32. gamma = 0.5.

#define NROWS 8192
#define DIM   256
#define BM    128
#define BN    128
#define NTHREADS 256
#define NBLK   304            // 2 persistent CTAs per SM
#define TPB    6              // 2080 = 304*6 + 256
#define TREM   256

// SMEM (bytes). fp8 tile: 128 rows x 256 B = 32 KB.
#define SM_A    0
#define SM_B0   32768
#define SM_B1   65536
#define SM_SQI  98304
#define SM_SQJ  (98304 + 512)
#define SM_RED  (98304 + 1024)
#define SMEM_TOTAL (98304 + 2048)

__device__ uint8_t  g_z8[NROWS * DIM];    // e4m3
__device__ float    g_sq[NROWS];
__device__ double   g_accum;              // term_a numerator  (reset by last block)
__device__ float    g_termb;              // sum exp(-sq/4)    (reset by last block)
__device__ unsigned g_done;               // ticket counter    (reset by last block)

// ---------------------------------------------------------------------------
__device__ __forceinline__ uint32_t smem_u32(const void* p) {
    uint32_t a;
    asm("{ .reg .u64 t; cvta.to.shared.u64 t, %1; cvt.u32.u64 %0, t; }"
        : "=r"(a) : "l"(p));
    return a;
}

__device__ __forceinline__ void cp16(uint32_t s, const void* g) {
    asm volatile("cp.async.cg.shared.global [%0], [%1], 16;"
                 :: "r"(s), "l"(g) : "memory");
}

__device__ __forceinline__ void ldsm4(uint32_t* r, uint32_t addr) {
    asm volatile("ldmatrix.sync.aligned.m8n8.x4.shared.b16 {%0,%1,%2,%3}, [%4];"
                 : "=r"(r[0]), "=r"(r[1]), "=r"(r[2]), "=r"(r[3])
                 : "r"(addr));
}

// accumulate form
__device__ __forceinline__ void mma_fp8_h(uint32_t* d, const uint32_t* a,
                                          const uint32_t* b) {
    asm volatile(
        "mma.sync.aligned.m16n8k32.row.col.f16.e4m3.e4m3.f16 "
        "{%0,%1}, {%2,%3,%4,%5}, {%6,%7}, {%0,%1};"
        : "+r"(d[0]), "+r"(d[1])
        : "r"(a[0]), "r"(a[1]), "r"(a[2]), "r"(a[3]),
          "r"(b[0]), "r"(b[1]));
}

// init form: c = {z,z} (zero), writes d without prior zeroing
__device__ __forceinline__ void mma_fp8_h_init(uint32_t* d, const uint32_t* a,
                                               const uint32_t* b, uint32_t z) {
    asm volatile(
        "mma.sync.aligned.m16n8k32.row.col.f16.e4m3.e4m3.f16 "
        "{%0,%1}, {%2,%3,%4,%5}, {%6,%7}, {%8,%8};"
        : "=r"(d[0]), "=r"(d[1])
        : "r"(a[0]), "r"(a[1]), "r"(a[2]), "r"(a[3]),
          "r"(b[0]), "r"(b[1]), "r"(z));
}

__device__ __forceinline__ uint32_t sw_off(int row, int kc16) {
    return (uint32_t)row * 256u + (uint32_t)((kc16 ^ (row & 7)) << 4);
}

__device__ __forceinline__ void load_tile(uint32_t dst, const uint8_t* src,
                                          int tid) {
    #pragma unroll
    for (int t = 0; t < 8; t++) {
        int idx = tid + t * NTHREADS;
        int row = idx >> 4;
        int kc  = idx & 15;
        cp16(dst + sw_off(row, kc), src + row * DIM + kc * 16);
    }
}

__device__ __forceinline__ void load_frags(uint32_t Abase, uint32_t Bbase,
                                           int kc0, int wm, int wn, int lane,
                                           uint32_t a[2][4], uint32_t b[4][4]) {
    #pragma unroll
    for (int mi = 0; mi < 2; mi++) {
        int row = wm + mi * 16 + (lane & 15);
        int kc  = kc0 + (lane >> 4);
        ldsm4(a[mi], Abase + sw_off(row, kc));
    }
    #pragma unroll
    for (int nq = 0; nq < 4; nq++) {
        int row = wn + nq * 16 + (lane & 7) + ((lane >> 4) << 3);
        int kc  = kc0 + ((lane >> 3) & 1);
        ldsm4(b[nq], Bbase + sw_off(row, kc));
    }
}

// exact fp32 recompute for screened-in pairs (cold path)
__device__ __noinline__ float exact_pair(const float* __restrict__ zf,
                                         int ig, int jg, float sqsum) {
    const float* zi = zf + (size_t)ig * DIM;
    const float* zj = zf + (size_t)jg * DIM;
    float dot = 0.0f;
    for (int k = 0; k < DIM; k++)
        dot = fmaf(zi[k], zj[k], dot);
    float de = fmaxf(sqsum - 2.0f * dot, 0.0f);
    return 2.0f * expf(-0.5f * de);
}

// ---------------------------------------------------------------------------
// Kernel 1: fp32 -> e4m3, exact fp32 row norms, term_b partial sums.
// ---------------------------------------------------------------------------
__global__ void __launch_bounds__(256) prep_kernel(const float* __restrict__ z)
{
    __shared__ float tb_red[8];

    const int w2   = (blockIdx.x * blockDim.x + threadIdx.x) >> 5;
    const int wloc = threadIdx.x >> 5;
    const int lane = threadIdx.x & 31;
    const int r0 = w2 * 2, r1 = r0 + 1;

    float tb = 0.0f;
    if (r0 < NROWS) {
        const float4* rowA = (const float4*)(z + (size_t)r0 * DIM);
        const float4* rowB = (const float4*)(z + (size_t)r1 * DIM);
        float4 a0 = rowA[lane * 2], b0 = rowA[lane * 2 + 1];
        float4 a1 = rowB[lane * 2], b1 = rowB[lane * 2 + 1];

        float s0 = a0.x*a0.x + a0.y*a0.y + a0.z*a0.z + a0.w*a0.w
                 + b0.x*b0.x + b0.y*b0.y + b0.z*b0.z + b0.w*b0.w;
        float s1 = a1.x*a1.x + a1.y*a1.y + a1.z*a1.z + a1.w*a1.w
                 + b1.x*b1.x + b1.y*b1.y + b1.z*b1.z + b1.w*b1.w;

        uint16_t p0, p1, p2, p3;
        asm("cvt.rn.satfinite.e4m3x2.f32 %0, %1, %2;" : "=h"(p0) : "f"(a0.y), "f"(a0.x));
        asm("cvt.rn.satfinite.e4m3x2.f32 %0, %1, %2;" : "=h"(p1) : "f"(a0.w), "f"(a0.z));
        asm("cvt.rn.satfinite.e4m3x2.f32 %0, %1, %2;" : "=h"(p2) : "f"(b0.y), "f"(b0.x));
        asm("cvt.rn.satfinite.e4m3x2.f32 %0, %1, %2;" : "=h"(p3) : "f"(b0.w), "f"(b0.z));
        uint2 pk0;
        pk0.x = (uint32_t)p0 | ((uint32_t)p1 << 16);
        pk0.y = (uint32_t)p2 | ((uint32_t)p3 << 16);
        *(uint2*)(g_z8 + (size_t)r0 * DIM + lane * 8) = pk0;

        asm("cvt.rn.satfinite.e4m3x2.f32 %0, %1, %2;" : "=h"(p0) : "f"(a1.y), "f"(a1.x));
        asm("cvt.rn.satfinite.e4m3x2.f32 %0, %1, %2;" : "=h"(p1) : "f"(a1.w), "f"(a1.z));
        asm("cvt.rn.satfinite.e4m3x2.f32 %0, %1, %2;" : "=h"(p2) : "f"(b1.y), "f"(b1.x));
        asm("cvt.rn.satfinite.e4m3x2.f32 %0, %1, %2;" : "=h"(p3) : "f"(b1.w), "f"(b1.z));
        uint2 pk1;
        pk1.x = (uint32_t)p0 | ((uint32_t)p1 << 16);
        pk1.y = (uint32_t)p2 | ((uint32_t)p3 << 16);
        *(uint2*)(g_z8 + (size_t)r1 * DIM + lane * 8) = pk1;

        #pragma unroll
        for (int o = 16; o > 0; o >>= 1) {
            s0 += __shfl_xor_sync(0xFFFFFFFFu, s0, o);
            s1 += __shfl_xor_sync(0xFFFFFFFFu, s1, o);
        }
        if (lane == 0) {
            g_sq[r0] = s0; g_sq[r1] = s1;
            tb = __expf(-0.25f * s0) + __expf(-0.25f * s1);
        }
    }

    if (lane == 0) tb_red[wloc] = tb;
    __syncthreads();
    if (threadIdx.x == 0) {
        float s = 0.0f;
        #pragma unroll
        for (int i = 0; i < 8; i++) s += tb_red[i];
        atomicAdd(&g_termb, s);
    }
}

// ---------------------------------------------------------------------------
// Kernel 2: persistent symmetric Gram + fused last-block finalize.
// ---------------------------------------------------------------------------
__global__ void __launch_bounds__(NTHREADS, 2)
gram_kernel(const float* __restrict__ zf, float* __restrict__ out)
{
    const int p = blockIdx.x;
    const int t0  = p * TPB + (p < TREM ? p : TREM);
    const int cnt = TPB + (p < TREM ? 1 : 0);
    const int t1  = t0 + cnt;

    extern __shared__ char smem[];
    const uint32_t sb  = smem_u32(smem);
    const int tid  = threadIdx.x;
    const int wid  = tid >> 5;
    const int lane = tid & 31;

    int bi = 0, s = 0;
    while (s + (64 - bi) <= t0) { s += 64 - bi; bi++; }
    int bj = bi + (t0 - s);

    float* sqi_s = (float*)(smem + SM_SQI);
    float* sqj_s = (float*)(smem + SM_SQJ);

    load_tile(sb + SM_B0, g_z8 + (size_t)bj * BN * DIM, tid);
    asm volatile("cp.async.commit_group;" ::: "memory");

    const int wm = (wid & 3) * 32;
    const int wn = (wid >> 2) * 64;
    const int t4 = lane >> 2;
    const int t2 = (lane & 3) << 1;

    int   loaded_bi = -1;
    int   buf = 0;
    float local = 0.0f;

    for (int t = t0; t < t1; t++) {
        asm volatile("cp.async.wait_group 0;" ::: "memory");
        __syncthreads();

        const bool a_new = (bi != loaded_bi);
        if (a_new) {
            load_tile(sb + SM_A, g_z8 + (size_t)bi * BM * DIM, tid);
            asm volatile("cp.async.commit_group;" ::: "memory");
            loaded_bi = bi;
            if (tid < 128) sqi_s[tid] = g_sq[bi * BM + tid];
        }
        if (tid < 128) sqj_s[tid] = g_sq[bj * BN + tid];

        int nbi = bi, nbj = bj + 1;
        if (nbj == 64) { nbi = bi + 1; nbj = nbi; }
        if (t + 1 < t1) {
            load_tile(sb + (buf ? SM_B0 : SM_B1),
                      g_z8 + (size_t)nbj * BN * DIM, tid);
            asm volatile("cp.async.commit_group;" ::: "memory");
        }
        if (a_new)
            asm volatile("cp.async.wait_group 1;" ::: "memory");
        __syncthreads();

        const bool diag = (bi == bj);
        if (!(diag && wn + 64 <= wm)) {
            const uint32_t Abase = sb + SM_A;
            const uint32_t Bbase = sb + (buf ? SM_B1 : SM_B0);

            uint32_t acc[2][8][2];
            uint32_t afr[2][2][4], bfr[2][4][4];
            load_frags(Abase, Bbase, 0, wm, wn, lane, afr[0], bfr[0]);

            const uint32_t z0 = 0u;
            #pragma unroll
            for (int ks = 0; ks < 8; ks++) {
                const int cur = ks & 1, nxt = cur ^ 1;
                if (ks < 7)
                    load_frags(Abase, Bbase, (ks + 1) * 2, wm, wn, lane,
                               afr[nxt], bfr[nxt]);
                if (ks == 0) {
                    #pragma unroll
                    for (int mi = 0; mi < 2; mi++)
                        #pragma unroll
                        for (int nq = 0; nq < 4; nq++) {
                            mma_fp8_h_init(acc[mi][nq*2],   afr[0][mi], &bfr[0][nq][0], z0);
                            mma_fp8_h_init(acc[mi][nq*2+1], afr[0][mi], &bfr[0][nq][2], z0);
                        }
                } else {
                    #pragma unroll
                    for (int mi = 0; mi < 2; mi++)
                        #pragma unroll
                        for (int nq = 0; nq < 4; nq++) {
                            mma_fp8_h(acc[mi][nq*2],   afr[cur][mi], &bfr[cur][nq][0]);
                            mma_fp8_h(acc[mi][nq*2+1], afr[cur][mi], &bfr[cur][nq][2]);
                        }
                }
            }

            // ---- cheap conservative screen ------------------------------
            // dmin_est = min_ni( sqi_min + sqj2[ni] - 2*max_acc[ni] )
            // <= true elementwise min d  (conservative superset trigger).
            float sqi0 = sqi_s[wm + t4];
            float sqi1 = sqi_s[wm + t4 + 8];
            float sqi2f = sqi_s[wm + 16 + t4];
            float sqi3 = sqi_s[wm + 16 + t4 + 8];
            float sqi_min = fminf(fminf(sqi0, sqi1), fminf(sqi2f, sqi3));
            const __half2 sqim2 = __float2half2_rn(sqi_min);
            const __half2 m2    = __float2half2_rn(-2.0f);

            __half2 dmin = __float2half2_rn(60000.0f);
            #pragma unroll
            for (int ni = 0; ni < 8; ni++) {
                int jl0 = wn + ni * 8 + t2;
                __half2 sqj2 = __floats2half2_rn(sqj_s[jl0], sqj_s[jl0 + 1]);
                __half2 amax = __hmax2(
                    __hmax2(*(const __half2*)&acc[0][ni][0],
                            *(const __half2*)&acc[0][ni][1]),
                    __hmax2(*(const __half2*)&acc[1][ni][0],
                            *(const __half2*)&acc[1][ni][1]));
                __half2 d2 = __hfma2(m2, amax, __hadd2(sqim2, sqj2));
                dmin = __hmin2(dmin, d2);
            }
            float dm = fminf(__low2float(dmin), __high2float(dmin));

            if (diag || dm < 250.0f) {
                // ---- slow path: scalar, exact where it matters ----------
                #pragma unroll
                for (int mi = 0; mi < 2; mi++)
                    #pragma unroll
                    for (int ni = 0; ni < 8; ni++)
                        #pragma unroll
                        for (int r = 0; r < 2; r++) {
                            float2 f = __half22float2(
                                *(const __half2*)&acc[mi][ni][r]);
                            int il = wm + mi * 16 + t4 + r * 8;
                            #pragma unroll
                            for (int c = 0; c < 2; c++) {
                                int jl = wn + ni * 8 + t2 + c;
                                float dot = (c == 0) ? f.x : f.y;
                                float ss  = sqi_s[il] + sqj_s[jl];
                                float d   = fmaf(-2.0f, dot, ss);
                                if (d < 250.0f) {
                                    int ig = bi * BM + il, jg = bj * BN + jl;
                                    if (ig == jg) local += 1.0f;
                                    else if (!diag || jl > il)
                                        local += exact_pair(zf, ig, jg, ss);
                                }
                            }
                        }
            }
        }

        bi = nbi; bj = nbj; buf ^= 1;
    }

    // block reduce + one double atomic; last block finalizes and resets
    float* red = (float*)(smem + SM_RED);
    red[tid] = local;
    __syncthreads();
    #pragma unroll
    for (int s2 = NTHREADS / 2; s2 > 0; s2 >>= 1) {
        if (tid < s2) red[tid] += red[tid + s2];
        __syncthreads();
    }
    if (tid == 0) {
        atomicAdd(&g_accum, (double)red[0]);
        __threadfence();
        unsigned ticket = atomicAdd(&g_done, 1u);
        if (ticket == NBLK - 1) {
            __threadfence();
            const double n = (double)NROWS;
            double term_a  = g_accum / (n * n);
            double term_b  = ldexp((double)g_termb / n, -128);
            double term_c  = 1.0 / pow(3.0, 128.0);
            out[0] = (float)(term_a - 2.0 * term_b + term_c);
            g_accum = 0.0;
            g_termb = 0.0f;
            g_done  = 0u;
        }
    }
}

// ---------------------------------------------------------------------------
extern "C" void kernel_launch(void* const* d_in, const int* in_sizes, int n_in,
                              void* d_out, int out_size)
{
    const float* z   = (const float*)d_in[0];
    float*       out = (float*)d_out;

    cudaFuncSetAttribute(gram_kernel,
                         cudaFuncAttributeMaxDynamicSharedMemorySize, SMEM_TOTAL);

    prep_kernel<<<NROWS / 16, 256>>>(z);

    gram_kernel<<<NBLK, NTHREADS, SMEM_TOTAL>>>(z, out);
}